// round 14
// baseline (speedup 1.0000x reference)
#include <cuda_runtime.h>
#include <cstdint>

namespace {
constexpr int H = 64, W = 64;
constexpr int C = 384;   // 48 positions * 8 channels
constexpr int B = 32;
constexpr int PLANES = B * C;          // 12288
constexpr int AP = 72;   // smem row pitch (floats)
constexpr int AR = 68;   // logical rows/cols of padded+displaced tile
constexpr int GRID = 740;              // 5 CTAs/SM * 148 SMs, persistent
}

// 5-tap normalized gaussian from fractional offset sub, sigma=0.5.
__device__ __forceinline__ void gauss5(float sub, float w[5]) {
  const float c1 = 0.135335283236612692f;    // exp(-2)
  const float c2 = 3.35462627902511839e-4f;  // exp(-8)
  float t  = __expf(-4.0f * sub);
  float it = 1.0f / t;
  float e0 = c2 * it * it;
  float e1 = c1 * it;
  float e2 = 1.0f;
  float e3 = c1 * t;
  float e4 = c2 * t * t;
  float inv = 1.0f / (e0 + e1 + e2 + e3 + e4);
  w[0] = e0 * inv; w[1] = e1 * inv; w[2] = e2 * inv;
  w[3] = e3 * inv; w[4] = e4 * inv;
}

__device__ __forceinline__ void cp_async8(uint32_t dst, const float* src, int srcsz) {
  asm volatile("cp.async.ca.shared.global [%0], [%1], 8, %2;"
               :: "r"(dst), "l"(src), "r"(srcsz));
}
__device__ __forceinline__ void cp_async4(uint32_t dst, const float* src, int srcsz) {
  asm volatile("cp.async.ca.shared.global [%0], [%1], 4, %2;"
               :: "r"(dst), "l"(src), "r"(srcsz));
}

__global__ __launch_bounds__(256) void displace_gauss_kernel(
    const float* __restrict__ x, const float* __restrict__ offset,
    float* __restrict__ out) {
  __shared__ __align__(16) float A[2][AR * AP];

  const int tid = threadIdx.x;

  // --- zero the 2-wide halo of both buffers once (never rewritten) ---
  if (tid < AR) {
#pragma unroll
    for (int b = 0; b < 2; b++) {
      float* Ab = A[b];
      Ab[0 * AP + tid] = 0.f;  Ab[1 * AP + tid] = 0.f;
      Ab[66 * AP + tid] = 0.f; Ab[67 * AP + tid] = 0.f;
      float* row = &Ab[tid * AP];
      row[0] = 0.f; row[1] = 0.f; row[66] = 0.f; row[67] = 0.f;
    }
  }

  const int fx = tid & 15;              // fill: float4 col group
  const int fy = tid >> 4;              // fill: row phase (4 passes)
  const int px = fx * 4;

  // issue async fill of `plane` into buffer `b`
  auto fill = [&](int b, int plane) {
    const int p = (plane % C) >> 3;
    const float ox = __ldg(&offset[2 * p + 0]);
    const float oy = __ldg(&offset[2 * p + 1]);
    const int dx = (int)rintf(ox);
    const int dy = (int)rintf(oy);
    const float* __restrict__ src = x + (size_t)plane * (H * W);
    if ((dx & 3) == 0) {
      const int sx = px - dx;           // multiple of 4
      const bool sxok = (unsigned)sx <= (unsigned)(W - 4);
#pragma unroll
      for (int i = 0; i < 4; i++) {
        const int py = fy + i * 16;
        const int sy = py - dy;
        const bool ok = sxok && ((unsigned)sy < (unsigned)H);
        const float* sp = ok ? &src[sy * W + sx] : src;  // clamped when dead
        const int sz = ok ? 8 : 0;                       // 0 => zero-fill
        uint32_t d = (uint32_t)__cvta_generic_to_shared(
            &A[b][(2 + py) * AP + 2 + px]);              // 8B-aligned
        cp_async8(d,     sp,     sz);
        cp_async8(d + 8, sp + 2, sz);
      }
    } else {
      // generic scalar path (not taken for this problem's offset grid)
#pragma unroll
      for (int i = 0; i < 4; i++) {
        const int py = fy + i * 16;
        const int sy = py - dy;
        const bool syok = (unsigned)sy < (unsigned)H;
        uint32_t d = (uint32_t)__cvta_generic_to_shared(
            &A[b][(2 + py) * AP + 2 + px]);
#pragma unroll
        for (int u = 0; u < 4; u++) {
          const int sxu = px + u - dx;
          const bool ok = syok && ((unsigned)sxu < (unsigned)W);
          const float* sp = ok ? &src[sy * W + sxu] : src;
          cp_async4(d + 4 * u, sp, ok ? 4 : 0);
        }
      }
    }
  };

  // --- conv tile coordinates (4 wide x 4 tall), R5-proven epilogue ---
  const int x0 = (tid & 15) * 4;
  const int y0 = (tid >> 4) * 4;

  int plane = blockIdx.x;
  if (plane >= PLANES) return;          // (GRID < PLANES, never taken)
  int buf = 0;
  fill(0, plane);
  asm volatile("cp.async.commit_group;");

  for (;;) {
    const int next = plane + GRID;
    const bool hasNext = next < PLANES;
    if (hasNext) {
      fill(buf ^ 1, next);
      asm volatile("cp.async.commit_group;");
      asm volatile("cp.async.wait_group 1;");
    } else {
      asm volatile("cp.async.wait_group 0;");
    }
    __syncthreads();                    // fill(plane) visible to all

    // --- conv + store for `plane` from A[buf] ---
    {
      const int p = (plane % C) >> 3;
      const float ox = __ldg(&offset[2 * p + 0]);
      const float oy = __ldg(&offset[2 * p + 1]);
      const float rxv = rintf(ox), ryv = rintf(oy);
      const int dx = (int)rxv, dy = (int)ryv;
      float* __restrict__ dst = out + (size_t)plane * (H * W);

      const int cx0 = dx > 0 ? dx : 0;
      const int cx1 = dx < 0 ? (W - 1 + dx) : (W - 1);
      const int cy0 = dy > 0 ? dy : 0;
      const int cy1 = dy < 0 ? (H - 1 + dy) : (H - 1);
      const bool live = (x0 + 5 >= cx0) & (x0 - 2 <= cx1) &
                        (y0 + 5 >= cy0) & (y0 - 2 <= cy1);
      if (!live) {                      // tile exactly zero; stay for barriers
        const float4 z = make_float4(0.f, 0.f, 0.f, 0.f);
#pragma unroll
        for (int o = 0; o < 4; o++)
          __stcs(reinterpret_cast<float4*>(&dst[(y0 + o) * W + x0]), z);
      } else {
        float wx[5], wy[5];
        gauss5(ox - rxv, wx);
        gauss5(oy - ryv, wy);
        const float* __restrict__ Ab = A[buf];
        float acc[4][4];
#pragma unroll
        for (int o = 0; o < 4; o++)
#pragma unroll
          for (int u = 0; u < 4; u++) acc[o][u] = 0.f;
#pragma unroll
        for (int r = 0; r < 8; r++) {   // 8 h-rows feed 4 output rows
          const float* row = &Ab[(y0 + r) * AP + x0];
          float4 a0 = *reinterpret_cast<const float4*>(row);
          float4 a1 = *reinterpret_cast<const float4*>(row + 4);
          float a[8] = {a0.x, a0.y, a0.z, a0.w, a1.x, a1.y, a1.z, a1.w};
          float h[4];
#pragma unroll
          for (int u = 0; u < 4; u++)
            h[u] = wx[0] * a[u] + wx[1] * a[u + 1] + wx[2] * a[u + 2]
                 + wx[3] * a[u + 3] + wx[4] * a[u + 4];
#pragma unroll
          for (int o = 0; o < 4; o++) {
            int i = r - o;              // compile-time pruned
            if (i >= 0 && i < 5) {
              float wv = wy[i];
#pragma unroll
              for (int u = 0; u < 4; u++) acc[o][u] += wv * h[u];
            }
          }
        }
#pragma unroll
        for (int o = 0; o < 4; o++) {
          float4 v = make_float4(acc[o][0], acc[o][1], acc[o][2], acc[o][3]);
          __stcs(reinterpret_cast<float4*>(&dst[(y0 + o) * W + x0]), v);
        }
      }
    }

    if (!hasNext) break;
    __syncthreads();                    // all done reading A[buf] before reuse
    plane = next;
    buf ^= 1;
  }
}

extern "C" void kernel_launch(void* const* d_in, const int* in_sizes, int n_in,
                              void* d_out, int out_size) {
  const float* x = (const float*)d_in[0];
  const float* offset = (const float*)d_in[1];
  float* out = (float*)d_out;
  displace_gauss_kernel<<<GRID, 256>>>(x, offset, out);
}

// round 15
// speedup vs baseline: 1.1152x; 1.1152x over previous
#include <cuda_runtime.h>
#include <cstdint>

namespace {
constexpr int H = 64, W = 64;
constexpr int C = 384;   // 48 positions * 8 channels
constexpr int B = 32;
constexpr int AP = 72;   // smem row pitch (floats), 288B -> 16B-aligned rows
constexpr int AR = 68;   // logical rows/cols of padded+displaced tile
}

// 5-tap normalized gaussian from fractional offset sub, sigma=0.5.
__device__ __forceinline__ void gauss5(float sub, float w[5]) {
  const float c1 = 0.135335283236612692f;    // exp(-2)
  const float c2 = 3.35462627902511839e-4f;  // exp(-8)
  float t  = __expf(-4.0f * sub);
  float it = 1.0f / t;
  float e0 = c2 * it * it;
  float e1 = c1 * it;
  float e2 = 1.0f;
  float e3 = c1 * t;
  float e4 = c2 * t * t;
  float inv = 1.0f / (e0 + e1 + e2 + e3 + e4);
  w[0] = e0 * inv; w[1] = e1 * inv; w[2] = e2 * inv;
  w[3] = e3 * inv; w[4] = e4 * inv;
}

__global__ __launch_bounds__(256) void displace_gauss_kernel(
    const float* __restrict__ x, const float* __restrict__ offset,
    float* __restrict__ out) {
  __shared__ __align__(16) float A[AR * AP];
  __shared__ __align__(16) float OUT[H * W];   // staged output plane (16KB)
  __shared__ float swx[5], swy[5];

  const int plane = blockIdx.x;         // b*C + c
  const int c = plane % C;
  const int p = c >> 3;                 // 8 channels per position
  const int tid = threadIdx.x;

  // --- every thread computes integer offset itself (broadcast loads) ---
  const float ox = __ldg(&offset[2 * p + 0]);
  const float oy = __ldg(&offset[2 * p + 1]);
  const float rxv = rintf(ox), ryv = rintf(oy);   // matches jnp.round
  const int dx = (int)rxv;
  const int dy = (int)ryv;

  // --- Gaussian weights: lane 0 does x-axis, lane 1 does y-axis ---
  if (tid < 2) {
    float w[5];
    gauss5((tid == 0) ? (ox - rxv) : (oy - ryv), w);
    float* d = (tid == 0) ? swx : swy;
#pragma unroll
    for (int j = 0; j < 5; j++) d[j] = w[j];
  }

  // --- zero the 2-wide halo (always zero: px/py out of [0,64) there) ---
  if (tid < AR) {
    A[0 * AP + tid] = 0.f;  A[1 * AP + tid] = 0.f;
    A[66 * AP + tid] = 0.f; A[67 * AP + tid] = 0.f;
    float* row = &A[tid * AP];
    row[0] = 0.f; row[1] = 0.f; row[66] = 0.f; row[67] = 0.f;
  }

  // --- fill 64x64 interior (R5-proven __ldcs float4 path) ---
  const float* __restrict__ src = x + (size_t)plane * (H * W);
  const int fx = tid & 15;              // float4 column index 0..15
  const int fy = tid >> 4;              // row 0..15 (4 strided passes)
  const int px = fx * 4;
  float* __restrict__ dstA = &A[(2 + fy) * AP + 2 + px];

  if ((dx & 3) == 0) {
    // vector path: displaced float4 stays aligned & validity is all-or-none
    const int sx = px - dx;             // multiple of 4
    const bool sxok = (unsigned)sx <= (unsigned)(W - 4);
#pragma unroll
    for (int i = 0; i < 4; i++) {
      const int sy = fy + i * 16 - dy;
      float4 v = make_float4(0.f, 0.f, 0.f, 0.f);
      if (sxok && (unsigned)sy < (unsigned)H)
        v = __ldcs(reinterpret_cast<const float4*>(&src[sy * W + sx]));
      float* d = dstA + i * 16 * AP;    // col 2+4k: 8B-aligned -> STS.64 x2
      *reinterpret_cast<float2*>(d + 0) = make_float2(v.x, v.y);
      *reinterpret_cast<float2*>(d + 2) = make_float2(v.z, v.w);
    }
  } else {
    // generic scalar path (not taken for this problem's offset grid)
#pragma unroll
    for (int i = 0; i < 4; i++) {
      const int sy = fy + i * 16 - dy;
      const bool syok = (unsigned)sy < (unsigned)H;
#pragma unroll
      for (int u = 0; u < 4; u++) {
        const int sxu = px + u - dx;
        float v = 0.f;
        if (syok && (unsigned)sxu < (unsigned)W) v = __ldcs(&src[sy * W + sxu]);
        dstA[i * 16 * AP + u] = v;
      }
    }
  }
  __syncthreads();

  // --- per-thread output tile coordinates (4 wide x 4 tall) ---
  const int txi = tid & 15;             // 16 x-tiles of width 4
  const int tyi = tid >> 4;             // 16 y-tiles of height 4
  const int x0 = txi * 4;
  const int y0 = tyi * 4;
  float* __restrict__ sout = &OUT[y0 * W + x0];

  // --- liveness: does this tile's input window touch any valid pixel? ---
  {
    const int cx0 = dx > 0 ? dx : 0;
    const int cx1 = dx < 0 ? (W - 1 + dx) : (W - 1);
    const int cy0 = dy > 0 ? dy : 0;
    const int cy1 = dy < 0 ? (H - 1 + dy) : (H - 1);
    const bool live = (x0 + 5 >= cx0) & (x0 - 2 <= cx1) &
                      (y0 + 5 >= cy0) & (y0 - 2 <= cy1);
    if (!live) {                        // entire tile is exactly zero
      const float4 z = make_float4(0.f, 0.f, 0.f, 0.f);
#pragma unroll
      for (int o = 0; o < 4; o++)
        *reinterpret_cast<float4*>(sout + o * W) = z;
      goto drain;                       // still participates in barriers
    }
  }

  {
    const float wx0 = swx[0], wx1 = swx[1], wx2 = swx[2], wx3 = swx[3],
                wx4 = swx[4];
    float wy[5];
#pragma unroll
    for (int i = 0; i < 5; i++) wy[i] = swy[i];

    float acc[4][4];
#pragma unroll
    for (int o = 0; o < 4; o++)
#pragma unroll
      for (int u = 0; u < 4; u++) acc[o][u] = 0.f;

#pragma unroll
    for (int r = 0; r < 8; r++) {       // 8 h-rows feed 4 output rows
      const float* row = &A[(y0 + r) * AP + x0];
      float4 a0 = *reinterpret_cast<const float4*>(row);
      float4 a1 = *reinterpret_cast<const float4*>(row + 4);
      float a[8] = {a0.x, a0.y, a0.z, a0.w, a1.x, a1.y, a1.z, a1.w};
      float h[4];
#pragma unroll
      for (int u = 0; u < 4; u++)
        h[u] = wx0 * a[u] + wx1 * a[u + 1] + wx2 * a[u + 2]
             + wx3 * a[u + 3] + wx4 * a[u + 4];
#pragma unroll
      for (int o = 0; o < 4; o++) {
        int i = r - o;                  // compile-time pruned
        if (i >= 0 && i < 5) {
          float wv = wy[i];
#pragma unroll
          for (int u = 0; u < 4; u++) acc[o][u] += wv * h[u];
        }
      }
    }

#pragma unroll
    for (int o = 0; o < 4; o++)
      *reinterpret_cast<float4*>(sout + o * W) =
          make_float4(acc[o][0], acc[o][1], acc[o][2], acc[o][3]);
  }

drain:
  // make generic-proxy STS visible to the async (TMA) proxy, then sync
  asm volatile("fence.proxy.async.shared::cta;" ::: "memory");
  __syncthreads();

  // one bulk store drains the whole contiguous output plane (16 KB)
  if (tid == 0) {
    uint32_t s = (uint32_t)__cvta_generic_to_shared(OUT);
    float* g = out + (size_t)plane * (H * W);
    asm volatile(
        "cp.async.bulk.global.shared::cta.bulk_group [%0], [%1], %2;"
        :: "l"(g), "r"(s), "r"((int)(H * W * sizeof(float))) : "memory");
    asm volatile("cp.async.bulk.commit_group;" ::: "memory");
    asm volatile("cp.async.bulk.wait_group.read 0;" ::: "memory");
  }
  __syncthreads();                      // smem must outlive the bulk read
}

extern "C" void kernel_launch(void* const* d_in, const int* in_sizes, int n_in,
                              void* d_out, int out_size) {
  const float* x = (const float*)d_in[0];
  const float* offset = (const float*)d_in[1];
  float* out = (float*)d_out;
  displace_gauss_kernel<<<B * C, 256>>>(x, offset, out);
}